// round 1
// baseline (speedup 1.0000x reference)
#include <cuda_runtime.h>
#include <math.h>

#define N_TOKENS 16384
#define D_MODEL  4096
#define N_EXP    64
#define TOPK     2
#define LB_COEF  0.01f

// ---------------- device scratch (no allocations allowed) ----------------
__device__ float g_wT[D_MODEL * N_EXP];   // gate_w transposed: [d][e], 1 MB
__device__ float g_psum[N_EXP];           // sum over tokens of router prob per expert
__device__ int   g_cnt[N_EXP];            // top1 histogram

// ---------------- zero accumulators ----------------
__global__ void zero_kernel() {
    int e = threadIdx.x;
    if (e < N_EXP) { g_psum[e] = 0.0f; g_cnt[e] = 0; }
}

// ---------------- transpose gate_w [E][D] -> wT [D][E] ----------------
__global__ void transpose_kernel(const float* __restrict__ gate_w) {
    int i = blockIdx.x * blockDim.x + threadIdx.x;   // i < D*E
    if (i < D_MODEL * N_EXP) {
        int d = i >> 6;          // / 64
        int e = i & 63;
        g_wT[i] = gate_w[e * D_MODEL + d];   // coalesced writes
    }
}

// ---------------- main fused GEMM + softmax/top2 + reductions ----------------
// block: 256 threads; tile: 128 tokens x 64 experts; K chunk = 32
// thread micro-tile: 8 tokens x 4 experts
#define KC 32
#define TM 128
#define XP 132           // sX pitch (floats), 132*4 bytes 16B-aligned per row

__global__ __launch_bounds__(256, 1)
void router_kernel(const float* __restrict__ x,
                   float* __restrict__ out)   // out: weights | indices | loss
{
    __shared__ float SM[TM * 65];            // 8320 floats; reused: tiles then logits
    __shared__ float pb[N_EXP];
    __shared__ int   cb[N_EXP];

    float* sX = SM;                          // KC x XP   = 4224 floats
    float* sW = SM + KC * XP;                // KC x 64   = 2048 floats (16B aligned)

    const int tid = threadIdx.x;
    const int tx  = tid & 15;                // expert group: experts 4*tx..4*tx+3
    const int ty  = tid >> 4;                // token group : tokens 8*ty..8*ty+7
    const int t0  = blockIdx.x * TM;

    const float4* x4  = (const float4*)x;            // row pitch D/4 = 1024
    const float4* wT4 = (const float4*)g_wT;         // row pitch E/4 = 16

    float acc[8][4];
#pragma unroll
    for (int i = 0; i < 8; i++)
#pragma unroll
        for (int j = 0; j < 4; j++) acc[i][j] = 0.0f;

    for (int k0 = 0; k0 < D_MODEL; k0 += KC) {
        // ---- fill X tile: sX[kk][tt] = x[t0+tt][k0+kk]  (transpose on store)
#pragma unroll
        for (int r = 0; r < 4; r++) {
            int f   = tid + 256 * r;              // 0..1023
            int tt  = f >> 3;                     // 0..127
            int kkq = f & 7;                      // float4 index within chunk
            float4 v = x4[(size_t)(t0 + tt) * (D_MODEL / 4) + (k0 >> 2) + kkq];
            int base = (4 * kkq) * XP + tt;
            sX[base          ] = v.x;
            sX[base + XP     ] = v.y;
            sX[base + 2 * XP ] = v.z;
            sX[base + 3 * XP ] = v.w;
        }
        // ---- fill W tile: sW[kk][e] = wT[k0+kk][e]  (already transposed: float4 copy)
#pragma unroll
        for (int r = 0; r < 2; r++) {
            int f  = tid + 256 * r;               // 0..511
            int kk = f >> 4;                      // 0..31
            int eq = f & 15;
            ((float4*)sW)[kk * 16 + eq] = wT4[(size_t)(k0 + kk) * 16 + eq];
        }
        __syncthreads();

        // ---- compute
#pragma unroll
        for (int kk = 0; kk < KC; kk++) {
            float4 w  = ((float4*)sW)[kk * 16 + tx];
            float4 xa = *(const float4*)&sX[kk * XP + 8 * ty];
            float4 xb = *(const float4*)&sX[kk * XP + 8 * ty + 4];
            float xs[8] = {xa.x, xa.y, xa.z, xa.w, xb.x, xb.y, xb.z, xb.w};
            float ws[4] = {w.x, w.y, w.z, w.w};
#pragma unroll
            for (int i = 0; i < 8; i++)
#pragma unroll
                for (int j = 0; j < 4; j++)
                    acc[i][j] = fmaf(xs[i], ws[j], acc[i][j]);
        }
        __syncthreads();
    }

    // ---- dump logits to smem: SM[token][expert], pitch 65 (conflict-free scans)
#pragma unroll
    for (int i = 0; i < 8; i++)
#pragma unroll
        for (int j = 0; j < 4; j++)
            SM[(ty * 8 + i) * 65 + (tx * 4 + j)] = acc[i][j];

    if (tid < N_EXP) { pb[tid] = 0.0f; cb[tid] = 0; }
    __syncthreads();

    // ---- per-token softmax + top2 + outputs (one thread per token)
    if (tid < TM) {
        float* row = &SM[tid * 65];
        float m = row[0];
#pragma unroll 8
        for (int e = 1; e < N_EXP; e++) m = fmaxf(m, row[e]);

        float s = 0.0f;
#pragma unroll 8
        for (int e = 0; e < N_EXP; e++) {
            float v = expf(row[e] - m);
            row[e] = v;
            s += v;
        }
        float inv = 1.0f / s;

        float v1 = -1.0f, v2 = -1.0f;
        int   i1 = 0,     i2 = 0;
#pragma unroll 8
        for (int e = 0; e < N_EXP; e++) {
            float p = row[e] * inv;
            atomicAdd(&pb[e], p);
            if (p > v1)      { v2 = v1; i2 = i1; v1 = p; i1 = e; }
            else if (p > v2) { v2 = p;  i2 = e; }
        }

        float rinv = 1.0f / (v1 + v2);
        int tg = t0 + tid;
        out[tg * 2 + 0] = v1 * rinv;
        out[tg * 2 + 1] = v2 * rinv;
        out[2 * N_TOKENS + tg * 2 + 0] = (float)i1;
        out[2 * N_TOKENS + tg * 2 + 1] = (float)i2;
        atomicAdd(&cb[i1], 1);
    }
    __syncthreads();

    if (tid < N_EXP) {
        atomicAdd(&g_psum[tid], pb[tid]);
        atomicAdd(&g_cnt[tid],  cb[tid]);
    }
}

// ---------------- loss = 0.01 * sum_e (cnt_e/N) * (psum_e/N) ----------------
__global__ void loss_kernel(float* __restrict__ out) {
    __shared__ float red[N_EXP];
    int e = threadIdx.x;
    float f = (float)g_cnt[e] * (1.0f / N_TOKENS);
    float p = g_psum[e] * (1.0f / N_TOKENS);
    red[e] = f * p;
    __syncthreads();
    for (int s = 32; s > 0; s >>= 1) {
        if (e < s) red[e] += red[e + s];
        __syncthreads();
    }
    if (e == 0) out[4 * N_TOKENS] = LB_COEF * red[0];
}

// ---------------- launch ----------------
extern "C" void kernel_launch(void* const* d_in, const int* in_sizes, int n_in,
                              void* d_out, int out_size)
{
    const float* x      = (const float*)d_in[0];
    const float* gate_w = (const float*)d_in[1];
    float* out = (float*)d_out;

    zero_kernel<<<1, 64>>>();
    transpose_kernel<<<(D_MODEL * N_EXP + 255) / 256, 256>>>(gate_w);
    router_kernel<<<N_TOKENS / TM, 256>>>(x, out);
    loss_kernel<<<1, N_EXP>>>(out);
}

// round 2
// speedup vs baseline: 1.1558x; 1.1558x over previous
#include <cuda_runtime.h>
#include <math.h>

#define N_TOKENS 16384
#define D_MODEL  4096
#define N_EXP    64
#define LB_COEF  0.01f

#define KC 16                    // K chunk
#define TM 128                   // tokens per block
#define XP 132                   // sX row pitch (floats), 132*4 % 16 == 0
#define XTILE (KC * XP)          // 2112 floats
#define WTILE (KC * N_EXP)       // 1024 floats
#define BUF   (XTILE + WTILE)    // 3136 floats per pipeline buffer
#define NCHUNK (D_MODEL / KC)    // 256

// ---------------- packed f32x2 helpers ----------------
#define FMA2(d, a, b) \
    asm("fma.rn.f32x2 %0, %1, %2, %0;" : "+l"(d) : "l"(a), "l"(b))
#define PACKB(o, f) \
    asm("mov.b64 %0, {%1, %1};" : "=l"(o) : "r"(__float_as_uint(f)))
#define UNPACK2(lo, hi, v) \
    asm("mov.b64 {%0, %1}, %2;" : "=f"(lo), "=f"(hi) : "l"(v))

// ---------------- device scratch ----------------
__device__ float g_wT[D_MODEL * N_EXP];   // gate_w transposed [d][e]
__device__ float g_psum[N_EXP];
__device__ int   g_cnt[N_EXP];

// ---------------- prep: zero accumulators + transpose gate_w ----------------
__global__ void prep_kernel(const float* __restrict__ gate_w) {
    int i = blockIdx.x * blockDim.x + threadIdx.x;
    if (i < N_EXP) { g_psum[i] = 0.0f; g_cnt[i] = 0; }
    if (i < D_MODEL * N_EXP) {
        int d = i >> 6;
        int e = i & 63;
        g_wT[i] = gate_w[e * D_MODEL + d];   // coalesced writes
    }
}

// ---------------- fused GEMM (f32x2) + softmax/top2 + reductions ----------------
// 256 threads, tile 128 tokens x 64 experts, thread micro-tile 8x4 (4 token-pairs x 4)
__global__ __launch_bounds__(256, 1)
void router_kernel(const float* __restrict__ x,
                   float* __restrict__ out)
{
    __shared__ __align__(16) float SM[TM * 65];   // 8320 floats: 2 pipe bufs (6272) / logits
    __shared__ float pb[N_EXP];
    __shared__ int   cb[N_EXP];

    const int tid = threadIdx.x;
    const int tx  = tid & 15;                // experts 4*tx .. 4*tx+3
    const int ty  = tid >> 4;                // tokens  8*ty .. 8*ty+7
    const int t0  = blockIdx.x * TM;

    const float4* x4  = (const float4*)x;            // row pitch 1024
    const float4* wT4 = (const float4*)g_wT;         // row pitch 16

    unsigned long long acc[4][4];            // [token-pair][expert], packed f32x2
#pragma unroll
    for (int i = 0; i < 4; i++)
#pragma unroll
        for (int j = 0; j < 4; j++) acc[i][j] = 0ULL;

    // prefetch registers
    float4 rx[2], rw;

    // decode fill indices once
    const int xtt0 = (tid)        >> 2, xkq0 = (tid)        & 3;
    const int xtt1 = (tid + 256)  >> 2, xkq1 = (tid + 256)  & 3;
    const int wkk  = tid >> 4,          weq  = tid & 15;

    // ---- prologue: load + store chunk 0
    {
        rx[0] = x4[(size_t)(t0 + xtt0) * (D_MODEL / 4) + xkq0];
        rx[1] = x4[(size_t)(t0 + xtt1) * (D_MODEL / 4) + xkq1];
        rw    = wT4[(size_t)wkk * 16 + weq];
        float* sX = SM;
        float* sW = SM + XTILE;
        int b0 = (4 * xkq0) * XP + xtt0;
        sX[b0] = rx[0].x; sX[b0 + XP] = rx[0].y; sX[b0 + 2*XP] = rx[0].z; sX[b0 + 3*XP] = rx[0].w;
        int b1 = (4 * xkq1) * XP + xtt1;
        sX[b1] = rx[1].x; sX[b1 + XP] = rx[1].y; sX[b1 + 2*XP] = rx[1].z; sX[b1 + 3*XP] = rx[1].w;
        ((float4*)sW)[wkk * 16 + weq] = rw;
    }
    __syncthreads();

    // ---- pipelined main loop
    for (int c = 0; c < NCHUNK; c++) {
        // issue global loads for chunk c+1 (latency hidden by compute below)
        if (c + 1 < NCHUNK) {
            int k0 = (c + 1) * KC;
            rx[0] = x4[(size_t)(t0 + xtt0) * (D_MODEL / 4) + (k0 >> 2) + xkq0];
            rx[1] = x4[(size_t)(t0 + xtt1) * (D_MODEL / 4) + (k0 >> 2) + xkq1];
            rw    = wT4[(size_t)(k0 + wkk) * 16 + weq];
        }

        // compute on current buffer
        {
            const float* sX = SM + (c & 1) * BUF;
            const float* sW = sX + XTILE;
#pragma unroll
            for (int kk = 0; kk < KC; kk++) {
                const float4 w = *(const float4*)&sW[kk * 64 + 4 * tx];
                const ulonglong2 xa = *(const ulonglong2*)&sX[kk * XP + 8 * ty];
                const ulonglong2 xb = *(const ulonglong2*)&sX[kk * XP + 8 * ty + 4];
                unsigned long long w0, w1, w2, w3;
                PACKB(w0, w.x); PACKB(w1, w.y); PACKB(w2, w.z); PACKB(w3, w.w);
                FMA2(acc[0][0], xa.x, w0); FMA2(acc[0][1], xa.x, w1);
                FMA2(acc[0][2], xa.x, w2); FMA2(acc[0][3], xa.x, w3);
                FMA2(acc[1][0], xa.y, w0); FMA2(acc[1][1], xa.y, w1);
                FMA2(acc[1][2], xa.y, w2); FMA2(acc[1][3], xa.y, w3);
                FMA2(acc[2][0], xb.x, w0); FMA2(acc[2][1], xb.x, w1);
                FMA2(acc[2][2], xb.x, w2); FMA2(acc[2][3], xb.x, w3);
                FMA2(acc[3][0], xb.y, w0); FMA2(acc[3][1], xb.y, w1);
                FMA2(acc[3][2], xb.y, w2); FMA2(acc[3][3], xb.y, w3);
            }
        }

        // store chunk c+1 into the other buffer
        if (c + 1 < NCHUNK) {
            float* sX = SM + ((c + 1) & 1) * BUF;
            float* sW = sX + XTILE;
            int b0 = (4 * xkq0) * XP + xtt0;
            sX[b0] = rx[0].x; sX[b0 + XP] = rx[0].y; sX[b0 + 2*XP] = rx[0].z; sX[b0 + 3*XP] = rx[0].w;
            int b1 = (4 * xkq1) * XP + xtt1;
            sX[b1] = rx[1].x; sX[b1 + XP] = rx[1].y; sX[b1 + 2*XP] = rx[1].z; sX[b1 + 3*XP] = rx[1].w;
            ((float4*)sW)[wkk * 16 + weq] = rw;
        }
        __syncthreads();
    }

    // ---- dump logits: SM[token][expert], pitch 65 (conflict-free row scans)
#pragma unroll
    for (int i = 0; i < 4; i++)
#pragma unroll
        for (int j = 0; j < 4; j++) {
            float lo, hi;
            UNPACK2(lo, hi, acc[i][j]);
            SM[(ty * 8 + 2 * i    ) * 65 + (tx * 4 + j)] = lo;
            SM[(ty * 8 + 2 * i + 1) * 65 + (tx * 4 + j)] = hi;
        }

    if (tid < N_EXP) { pb[tid] = 0.0f; cb[tid] = 0; }
    __syncthreads();

    // ---- per-token softmax + top2 + outputs
    if (tid < TM) {
        float* row = &SM[tid * 65];
        float m = row[0];
#pragma unroll 8
        for (int e = 1; e < N_EXP; e++) m = fmaxf(m, row[e]);

        float s = 0.0f;
#pragma unroll 8
        for (int e = 0; e < N_EXP; e++) {
            float v = expf(row[e] - m);
            row[e] = v;
            s += v;
        }
        float inv = 1.0f / s;

        float v1 = -1.0f, v2 = -1.0f;
        int   i1 = 0,     i2 = 0;
#pragma unroll 8
        for (int e = 0; e < N_EXP; e++) {
            float p = row[e] * inv;
            atomicAdd(&pb[e], p);
            if (p > v1)      { v2 = v1; i2 = i1; v1 = p; i1 = e; }
            else if (p > v2) { v2 = p;  i2 = e; }
        }

        float rinv = 1.0f / (v1 + v2);
        int tg = t0 + tid;
        out[tg * 2 + 0] = v1 * rinv;
        out[tg * 2 + 1] = v2 * rinv;
        out[2 * N_TOKENS + tg * 2 + 0] = (float)i1;
        out[2 * N_TOKENS + tg * 2 + 1] = (float)i2;
        atomicAdd(&cb[i1], 1);
    }
    __syncthreads();

    if (tid < N_EXP) {
        atomicAdd(&g_psum[tid], pb[tid]);
        atomicAdd(&g_cnt[tid],  cb[tid]);
    }
}

// ---------------- loss = 0.01 * sum_e (cnt_e/N) * (psum_e/N) ----------------
__global__ void loss_kernel(float* __restrict__ out) {
    __shared__ float red[N_EXP];
    int e = threadIdx.x;
    float f = (float)g_cnt[e] * (1.0f / N_TOKENS);
    float p = g_psum[e] * (1.0f / N_TOKENS);
    red[e] = f * p;
    __syncthreads();
    for (int s = 32; s > 0; s >>= 1) {
        if (e < s) red[e] += red[e + s];
        __syncthreads();
    }
    if (e == 0) out[4 * N_TOKENS] = LB_COEF * red[0];
}

// ---------------- launch ----------------
extern "C" void kernel_launch(void* const* d_in, const int* in_sizes, int n_in,
                              void* d_out, int out_size)
{
    const float* x      = (const float*)d_in[0];
    const float* gate_w = (const float*)d_in[1];
    float* out = (float*)d_out;

    prep_kernel<<<(D_MODEL * N_EXP + 255) / 256, 256>>>(gate_w);
    router_kernel<<<N_TOKENS / TM, 256>>>(x, out);
    loss_kernel<<<1, N_EXP>>>(out);
}

// round 4
// speedup vs baseline: 3.1322x; 2.7100x over previous
#include <cuda_runtime.h>
#include <math.h>
#include <stdint.h>

#define N_TOKENS 16384
#define D_MODEL  4096
#define N_EXP    64
#define LB_COEF  0.01f

#define KC     32
#define NCHUNK (D_MODEL / KC)     // 128
#define TM     128
#define NCTA   (N_TOKENS / TM)    // 128
#define NTHR   256

// smem stage layout (float/uint32 indices), pitch 36 => conflict-free frag loads
#define PITCH   36
#define A_HI    0
#define A_LO    (128 * PITCH)               // 4608
#define B_HI    (2 * 128 * PITCH)           // 9216
#define B_LO    (B_HI + 64 * PITCH)         // 11520
#define STAGE_F (B_LO + 64 * PITCH)         // 13824 floats per stage
#define DYN_BYTES (2 * STAGE_F * 4)         // 110592 bytes

// ---------------- helpers ----------------
static __device__ __forceinline__ uint32_t tf32_of(float f) {
    uint32_t r;
    asm("cvt.rna.tf32.f32 %0, %1;" : "=r"(r) : "f"(f));
    return r;
}

static __device__ __forceinline__ void cvt4(float4 v, uint4& h, uint4& l) {
    h.x = tf32_of(v.x); h.y = tf32_of(v.y); h.z = tf32_of(v.z); h.w = tf32_of(v.w);
    l.x = tf32_of(v.x - __uint_as_float(h.x));
    l.y = tf32_of(v.y - __uint_as_float(h.y));
    l.z = tf32_of(v.z - __uint_as_float(h.z));
    l.w = tf32_of(v.w - __uint_as_float(h.w));
}

#define MMA(d, a, b)                                                     \
    asm volatile(                                                        \
        "mma.sync.aligned.m16n8k8.row.col.f32.tf32.tf32.f32 "            \
        "{%0,%1,%2,%3}, {%4,%5,%6,%7}, {%8,%9}, {%0,%1,%2,%3};"          \
        : "+f"((d)[0]), "+f"((d)[1]), "+f"((d)[2]), "+f"((d)[3])         \
        : "r"((a)[0]), "r"((a)[1]), "r"((a)[2]), "r"((a)[3]),            \
          "r"((b)[0]), "r"((b)[1]))

// ---------------- device scratch ----------------
__device__ float g_psum[N_EXP];
__device__ int   g_cnt[N_EXP];

__global__ void zero_kernel() {
    int e = threadIdx.x;
    if (e < N_EXP) { g_psum[e] = 0.0f; g_cnt[e] = 0; }
}

// ---------------- fused GEMM (3xTF32 mma.sync) + softmax/top2 ----------------
// 256 threads = 8 warps; CTA tile 128 tokens x 64 experts; warp tile 32x32.
__global__ __launch_bounds__(NTHR, 1)
void router_kernel(const float* __restrict__ x,
                   const float* __restrict__ gw,
                   float* __restrict__ out)
{
    extern __shared__ float dynsm[];
    __shared__ int cb[N_EXP];

    const int tid  = threadIdx.x;
    const int t0   = blockIdx.x * TM;
    const int lane = tid & 31;
    const int wid  = tid >> 5;
    const int wm   = wid >> 1;          // 0..3  -> token base wm*32
    const int wn   = wid & 1;           // 0..1  -> expert base wn*32
    const int lr   = lane >> 2;         // groupID
    const int lc   = lane & 3;          // threadID_in_group

    uint32_t* sm = (uint32_t*)dynsm;

    if (tid < N_EXP) cb[tid] = 0;

    // fill mapping: thread -> (row block, float4 col g)
    const int R = tid >> 3;             // 0..31
    const int g = tid & 7;              // 0..7

    const float4* x4 = (const float4*)x;     // row pitch 1024 float4
    const float4* w4 = (const float4*)gw;    // row pitch 1024 float4

    size_t xoff[4], woff[2];
#pragma unroll
    for (int k = 0; k < 4; k++) xoff[k] = (size_t)(t0 + R + 32 * k) * 1024 + g;
#pragma unroll
    for (int k = 0; k < 2; k++) woff[k] = (size_t)(R + 32 * k) * 1024 + g;

    float4 xa[4], wb[2];

    // ---- prologue: load chunk 0, convert, store to stage 0
#pragma unroll
    for (int k = 0; k < 4; k++) xa[k] = x4[xoff[k]];
#pragma unroll
    for (int k = 0; k < 2; k++) wb[k] = w4[woff[k]];
    {
        uint32_t* s = sm;
#pragma unroll
        for (int k = 0; k < 4; k++) {
            uint4 h, l; cvt4(xa[k], h, l);
            int o = (R + 32 * k) * PITCH + 4 * g;
            *(uint4*)(s + A_HI + o) = h;
            *(uint4*)(s + A_LO + o) = l;
        }
#pragma unroll
        for (int k = 0; k < 2; k++) {
            uint4 h, l; cvt4(wb[k], h, l);
            int o = (R + 32 * k) * PITCH + 4 * g;
            *(uint4*)(s + B_HI + o) = h;
            *(uint4*)(s + B_LO + o) = l;
        }
    }
    __syncthreads();

    float acc[2][4][4];
#pragma unroll
    for (int mi = 0; mi < 2; mi++)
#pragma unroll
        for (int ni = 0; ni < 4; ni++)
#pragma unroll
            for (int j = 0; j < 4; j++) acc[mi][ni][j] = 0.0f;

    // ---- main loop: double-buffered, one bar per chunk
    for (int c = 0; c < NCHUNK; c++) {
        if (c + 1 < NCHUNK) {
#pragma unroll
            for (int k = 0; k < 4; k++) xa[k] = x4[xoff[k] + (size_t)(c + 1) * 8];
#pragma unroll
            for (int k = 0; k < 2; k++) wb[k] = w4[woff[k] + (size_t)(c + 1) * 8];
        }

        const uint32_t* s = sm + (c & 1) * STAGE_F;
#pragma unroll
        for (int ks = 0; ks < 4; ks++) {
            uint32_t ah[2][4], al[2][4];
#pragma unroll
            for (int mi = 0; mi < 2; mi++) {
                int base = (wm * 32 + mi * 16 + lr) * PITCH + ks * 8 + lc;
                ah[mi][0] = s[A_HI + base];
                ah[mi][1] = s[A_HI + base + 8 * PITCH];
                ah[mi][2] = s[A_HI + base + 4];
                ah[mi][3] = s[A_HI + base + 8 * PITCH + 4];
                al[mi][0] = s[A_LO + base];
                al[mi][1] = s[A_LO + base + 8 * PITCH];
                al[mi][2] = s[A_LO + base + 4];
                al[mi][3] = s[A_LO + base + 8 * PITCH + 4];
            }
#pragma unroll
            for (int ni = 0; ni < 4; ni++) {
                int base = (wn * 32 + ni * 8 + lr) * PITCH + ks * 8 + lc;
                uint32_t bh[2] = { s[B_HI + base], s[B_HI + base + 4] };
                uint32_t bl[2] = { s[B_LO + base], s[B_LO + base + 4] };
#pragma unroll
                for (int mi = 0; mi < 2; mi++) {
                    MMA(acc[mi][ni], ah[mi], bh);
                    MMA(acc[mi][ni], al[mi], bh);
                    MMA(acc[mi][ni], ah[mi], bl);
                }
            }
        }

        if (c + 1 < NCHUNK) {
            uint32_t* d = sm + ((c + 1) & 1) * STAGE_F;
#pragma unroll
            for (int k = 0; k < 4; k++) {
                uint4 h, l; cvt4(xa[k], h, l);
                int o = (R + 32 * k) * PITCH + 4 * g;
                *(uint4*)(d + A_HI + o) = h;
                *(uint4*)(d + A_LO + o) = l;
            }
#pragma unroll
            for (int k = 0; k < 2; k++) {
                uint4 h, l; cvt4(wb[k], h, l);
                int o = (R + 32 * k) * PITCH + 4 * g;
                *(uint4*)(d + B_HI + o) = h;
                *(uint4*)(d + B_LO + o) = l;
            }
        }
        __syncthreads();
    }

    // ---- dump logits to smem G[128][65] (overlays stage 0; all reads done)
    float* G = dynsm;
#pragma unroll
    for (int mi = 0; mi < 2; mi++)
#pragma unroll
        for (int ni = 0; ni < 4; ni++) {
            int tr = wm * 32 + mi * 16 + lr;
            int ec = wn * 32 + ni * 8 + 2 * lc;
            G[tr * 65 + ec]           = acc[mi][ni][0];
            G[tr * 65 + ec + 1]       = acc[mi][ni][1];
            G[(tr + 8) * 65 + ec]     = acc[mi][ni][2];
            G[(tr + 8) * 65 + ec + 1] = acc[mi][ni][3];
        }
    __syncthreads();

    // ---- per-token softmax + top2; write normalized probs back into G
    if (tid < TM) {
        float* row = G + tid * 65;
        float m = row[0];
#pragma unroll 8
        for (int e = 1; e < N_EXP; e++) m = fmaxf(m, row[e]);

        float ssum = 0.0f;
#pragma unroll 8
        for (int e = 0; e < N_EXP; e++) {
            float v = expf(row[e] - m);
            row[e] = v;
            ssum += v;
        }
        float inv = 1.0f / ssum;

        float v1 = -1.0f, v2 = -1.0f;
        int   i1 = 0,     i2 = 0;
#pragma unroll 8
        for (int e = 0; e < N_EXP; e++) {
            float p = row[e] * inv;
            row[e] = p;
            if (p > v1)      { v2 = v1; i2 = i1; v1 = p; i1 = e; }
            else if (p > v2) { v2 = p;  i2 = e; }
        }

        float rn = 1.0f / (v1 + v2);
        int tg = t0 + tid;
        out[2 * tg]     = v1 * rn;
        out[2 * tg + 1] = v2 * rn;
        out[2 * N_TOKENS + 2 * tg]     = (float)i1;
        out[2 * N_TOKENS + 2 * tg + 1] = (float)i2;
        atomicAdd(&cb[i1], 1);
    }
    __syncthreads();

    // ---- per-expert prob sums over this block's tokens -> global
    if (tid < N_EXP) {
        float s = 0.0f;
#pragma unroll 8
        for (int t = 0; t < TM; t++) s += G[t * 65 + tid];
        atomicAdd(&g_psum[tid], s);
        atomicAdd(&g_cnt[tid], cb[tid]);
    }
}

// ---------------- loss = 0.01 * sum_e (cnt_e/N) * (psum_e/N) ----------------
__global__ void loss_kernel(float* __restrict__ out) {
    __shared__ float red[N_EXP];
    int e = threadIdx.x;
    red[e] = (float)g_cnt[e] * g_psum[e];
    __syncthreads();
    for (int s = 32; s > 0; s >>= 1) {
        if (e < s) red[e] += red[e + s];
        __syncthreads();
    }
    if (e == 0)
        out[4 * N_TOKENS] = LB_COEF * red[0] * (1.0f / N_TOKENS) * (1.0f / N_TOKENS);
}

// ---------------- launch ----------------
extern "C" void kernel_launch(void* const* d_in, const int* in_sizes, int n_in,
                              void* d_out, int out_size)
{
    const float* x  = (const float*)d_in[0];
    const float* gw = (const float*)d_in[1];
    float* out = (float*)d_out;

    cudaFuncSetAttribute(router_kernel,
                         cudaFuncAttributeMaxDynamicSharedMemorySize, DYN_BYTES);

    zero_kernel<<<1, N_EXP>>>();
    router_kernel<<<NCTA, NTHR, DYN_BYTES>>>(x, gw, out);
    loss_kernel<<<1, N_EXP>>>(out);
}